// round 6
// baseline (speedup 1.0000x reference)
#include <cuda_runtime.h>
#include <cstdint>

// Shapes fixed by reference setup_inputs
static constexpr int Bb = 8, Tt = 256, Uu = 64, Dd = 512, Aa = 256, Vv = 1024;
static constexpr long long Mm = (long long)Bb * Tt * Uu;   // 131072

// ---- global scratch (static __device__ arrays; allocation-free) ----
__device__ uint16_t g_Ahi[(size_t)Mm * Aa];     // split hptr
__device__ uint16_t g_Alo[(size_t)Mm * Aa];
__device__ uint16_t g_actHi[(size_t)Mm * Dd];   // split activation (k1 -> k2)
__device__ uint16_t g_actLo[(size_t)Mm * Dd];
__device__ uint16_t g_Wbhi[(size_t)Dd * Aa];
__device__ uint16_t g_Wblo[(size_t)Dd * Aa];
__device__ uint16_t g_Wohi[(size_t)Vv * Dd];
__device__ uint16_t g_Wolo[(size_t)Vv * Dd];

__device__ __forceinline__ float hif(float x) {
    return __uint_as_float(__float_as_uint(x) & 0xFFFF0000u);
}
__device__ __forceinline__ uint32_t pack2hi(float x, float y) {
    return __byte_perm(__float_as_uint(x), __float_as_uint(y), 0x7632);
}
__device__ __forceinline__ uint32_t smem_u32(const void* p) {
    uint32_t a;
    asm("{ .reg .u64 t; cvta.to.shared.u64 t, %1; cvt.u32.u64 %0, t; }" : "=r"(a) : "l"(p));
    return a;
}
__device__ __forceinline__ void cp16(uint32_t daddr, const void* src) {
    asm volatile("cp.async.cg.shared.global [%0], [%1], 16;"
                 :: "r"(daddr), "l"(src) : "memory");
}
__device__ __forceinline__ void ldsm4(uint32_t r[4], uint32_t addr) {
    asm volatile("ldmatrix.sync.aligned.m8n8.x4.shared.b16 {%0,%1,%2,%3}, [%4];"
                 : "=r"(r[0]), "=r"(r[1]), "=r"(r[2]), "=r"(r[3]) : "r"(addr));
}

#define MMA_BF16(c, a, b)                                                        \
    asm volatile(                                                                \
        "mma.sync.aligned.m16n8k16.row.col.f32.bf16.bf16.f32 "                   \
        "{%0,%1,%2,%3}, {%4,%5,%6,%7}, {%8,%9}, {%0,%1,%2,%3};"                  \
        : "+f"((c)[0]), "+f"((c)[1]), "+f"((c)[2]), "+f"((c)[3])                 \
        : "r"((a)[0]), "r"((a)[1]), "r"((a)[2]), "r"((a)[3]),                    \
          "r"((b)[0]), "r"((b)[1]))

// Split fp32 -> (hi, lo) bf16 pair (truncation; residual exact in fp32)
__global__ void split_kernel(const float4* __restrict__ in,
                             ushort4* __restrict__ hi, ushort4* __restrict__ lo,
                             long long n4)
{
    long long i = (long long)blockIdx.x * blockDim.x + threadIdx.x;
    if (i >= n4) return;
    float4 v = in[i];
    ushort4 h, l;
    h.x = (unsigned short)(__float_as_uint(v.x) >> 16);
    h.y = (unsigned short)(__float_as_uint(v.y) >> 16);
    h.z = (unsigned short)(__float_as_uint(v.z) >> 16);
    h.w = (unsigned short)(__float_as_uint(v.w) >> 16);
    l.x = (unsigned short)(__float_as_uint(v.x - hif(v.x)) >> 16);
    l.y = (unsigned short)(__float_as_uint(v.y - hif(v.y)) >> 16);
    l.z = (unsigned short)(__float_as_uint(v.z - hif(v.z)) >> 16);
    l.w = (unsigned short)(__float_as_uint(v.w - hif(v.w)) >> 16);
    hi[i] = h;
    lo[i] = l;
}

// NT GEMM, split-bf16 x3, pre-converted operands:
// C[m,n] = sum_k A[m,k]*B[n,k]; CTA tile 128(M) x 256(N), BK=32, 3-stage cp.async.
// 512 threads, 16 warps 4(M) x 4(N); warp tile 32 x 64.
// FUSE=1: C = relu(acc + src + tgt + bias), also emits split-bf16 act to scratch.
template <int K, int FUSE>
__global__ __launch_bounds__(512)
void mma_gemm(const uint16_t* __restrict__ Ahi, const uint16_t* __restrict__ Alo,
              const uint16_t* __restrict__ Bhi, const uint16_t* __restrict__ Blo,
              const float* __restrict__ bias,
              const float* __restrict__ src, const float* __restrict__ tgt,
              float* __restrict__ C,
              uint16_t* __restrict__ actHi, uint16_t* __restrict__ actLo,
              int N)
{
    constexpr int BK  = 32;
    constexpr int KB  = K / BK;
    constexpr int STAGES = 3;
    // per-stage byte offsets (row stride 80B = 16 data words + 4 pad)
    constexpr uint32_t AHI = 0;
    constexpr uint32_t ALO = 128 * 80;            // 10240
    constexpr uint32_t BHI = 2 * 128 * 80;        // 20480
    constexpr uint32_t BLO = BHI + 256 * 80;      // 40960
    constexpr uint32_t STAGE_BYTES = BLO + 256 * 80;   // 61440

    extern __shared__ uint32_t sw[];
    const uint32_t sbase = smem_u32(sw);

    const int tid  = threadIdx.x;
    const int wid  = tid >> 5;
    const int lane = tid & 31;
    const int gid  = lane >> 2;
    const int tig  = lane & 3;
    const int wm   = (wid & 3) * 32;
    const int wn   = (wid >> 2) * 64;
    const long long m0 = (long long)blockIdx.y * 128;
    const int n0 = blockIdx.x * 256;

    // ldmatrix lane addressing (validated in R5)
    const int a_row  = ((lane >> 3) & 1) * 8 + (lane & 7);
    const int a_koff = (lane >> 4) * 16;
    const int b_row  = (lane >> 4) * 8 + (lane & 7);
    const int b_koff = ((lane >> 3) & 1) * 16;
    const uint32_t aoff = (uint32_t)((wm + a_row) * 80 + a_koff);           // within AHI
    const uint32_t boff = BHI + (uint32_t)((wn + b_row) * 80 + b_koff);     // within stage

    float c[2][8][4];
#pragma unroll
    for (int i = 0; i < 2; i++)
#pragma unroll
        for (int j = 0; j < 8; j++)
#pragma unroll
            for (int t = 0; t < 4; t++) c[i][j][t] = 0.0f;

    // producer chunk mapping
    const int arow = tid >> 2;          // 0..127
    const int aq   = tid & 3;           // 0..3 (16B chunks of 64B row)

    auto load_stage = [&](int kb, int buf) {
        const uint32_t stg = sbase + (uint32_t)buf * STAGE_BYTES;
        {   // A: 128 rows x 64B per array
            const long long go = (m0 + arow) * (long long)K + kb * BK + aq * 8;
            cp16(stg + AHI + arow * 80 + aq * 16, Ahi + go);
            cp16(stg + ALO + arow * 80 + aq * 16, Alo + go);
        }
#pragma unroll
        for (int t = 0; t < 2; t++) {   // B: 256 rows x 64B per array
            const int ch  = tid + t * 512;
            const int row = ch >> 2;
            const int q   = ch & 3;
            const long long go = (long long)(n0 + row) * K + kb * BK + q * 8;
            cp16(stg + BHI + row * 80 + q * 16, Bhi + go);
            cp16(stg + BLO + row * 80 + q * 16, Blo + go);
        }
        asm volatile("cp.async.commit_group;" ::: "memory");
    };

    load_stage(0, 0);
    if (KB > 1) load_stage(1, 1);

    int cbuf = 0;
#pragma unroll 1
    for (int kb = 0; kb < KB; kb++) {
        asm volatile("cp.async.wait_group 1;" ::: "memory");
        __syncthreads();
        if (kb + STAGES - 1 < KB) {
            int lb = cbuf + 2; if (lb >= STAGES) lb -= STAGES;
            load_stage(kb + STAGES - 1, lb);
        }

        const uint32_t stg = sbase + (uint32_t)cbuf * STAGE_BYTES;

#pragma unroll
        for (int ks = 0; ks < 2; ks++) {
            const uint32_t kB = ks * 32;
            uint32_t ah[2][4], al[2][4];
#pragma unroll
            for (int mi = 0; mi < 2; mi++) {
                const uint32_t a0 = stg + aoff + mi * (16 * 80) + kB;
                ldsm4(ah[mi], a0);
                ldsm4(al[mi], a0 + ALO);
            }
#pragma unroll
            for (int p = 0; p < 4; p++) {
                uint32_t bh[4], bl[4];
                const uint32_t b0 = stg + boff + p * (16 * 80) + kB;
                ldsm4(bh, b0);
                ldsm4(bl, b0 + (BLO - BHI));
#pragma unroll
                for (int mi = 0; mi < 2; mi++)
#pragma unroll
                    for (int q = 0; q < 2; q++) {
                        MMA_BF16(c[mi][p * 2 + q], al[mi], &bh[q * 2]);   // lo*hi
                        MMA_BF16(c[mi][p * 2 + q], ah[mi], &bl[q * 2]);   // hi*lo
                        MMA_BF16(c[mi][p * 2 + q], ah[mi], &bh[q * 2]);   // hi*hi
                    }
            }
        }

        if (++cbuf == STAGES) cbuf = 0;
    }

    // Epilogue: rows gid / gid+8 (per mi), cols wn + p*16 + q*8 + 2*tig
#pragma unroll
    for (int mi = 0; mi < 2; mi++) {
#pragma unroll
        for (int half = 0; half < 2; half++) {
            const long long m = m0 + wm + mi * 16 + gid + half * 8;
            const float* srow = nullptr;
            const float* trow = nullptr;
            if (FUSE) {
                const int mi32 = (int)m;
                const int bi = mi32 / (Tt * Uu);
                const int r  = mi32 % (Tt * Uu);
                const int ti = r / Uu;
                const int ui = r % Uu;
                srow = src + (long long)(bi * Tt + ti) * Dd;
                trow = tgt + (long long)(bi * Uu + ui) * Dd;
            }
            float* crow = C + m * N;
#pragma unroll
            for (int nj = 0; nj < 8; nj++) {
                const int n = n0 + wn + nj * 8 + tig * 2;
                float2 bi2 = *(const float2*)(bias + n);
                float vx = c[mi][nj][half * 2 + 0] + bi2.x;
                float vy = c[mi][nj][half * 2 + 1] + bi2.y;
                if (FUSE) {
                    float2 s2 = *(const float2*)(srow + n);
                    float2 t2 = *(const float2*)(trow + n);
                    vx = fmaxf(vx + s2.x + t2.x, 0.0f);
                    vy = fmaxf(vy + s2.y + t2.y, 0.0f);
                }
                *(float2*)(crow + n) = make_float2(vx, vy);
                if (FUSE) {
                    const long long w = (m * N + n) >> 1;   // n even
                    ((uint32_t*)actHi)[w] = pack2hi(vx, vy);
                    ((uint32_t*)actLo)[w] = pack2hi(vx - hif(vx), vy - hif(vy));
                }
            }
        }
    }
}

// Pass-through of lengths, converted to the float32 output dtype.
__global__ void lengths_kernel(const int* __restrict__ sl, const int* __restrict__ tl,
                               float* __restrict__ out_sl, float* __restrict__ out_tl)
{
    int i = threadIdx.x;
    if (i < Bb) { out_sl[i] = (float)sl[i]; out_tl[i] = (float)tl[i]; }
}

extern "C" void kernel_launch(void* const* d_in, const int* in_sizes, int n_in,
                              void* d_out, int out_size)
{
    const float* src  = (const float*)d_in[0];   // (B, T, D)
    const int*   sl   = (const int*)  d_in[1];
    const float* tgt  = (const float*)d_in[2];   // (B, U, D)
    const int*   tl   = (const int*)  d_in[3];
    const float* hptr = (const float*)d_in[4];   // (M, A)
    const float* Wb   = (const float*)d_in[5];   // (D, A)
    const float* bb   = (const float*)d_in[6];
    const float* Wo   = (const float*)d_in[7];   // (V, D)
    const float* bo   = (const float*)d_in[8];

    float* out = (float*)d_out;
    const long long OFF_SL  = Mm * Vv;
    const long long OFF_TL  = OFF_SL + Bb;
    const long long OFF_ACT = OFF_TL + Bb;
    float* out_main = out;
    float* out_act  = out + OFF_ACT;

    // scratch pointers
    uint16_t *pAhi, *pAlo, *pActHi, *pActLo, *pWbhi, *pWblo, *pWohi, *pWolo;
    cudaGetSymbolAddress((void**)&pAhi,   g_Ahi);
    cudaGetSymbolAddress((void**)&pAlo,   g_Alo);
    cudaGetSymbolAddress((void**)&pActHi, g_actHi);
    cudaGetSymbolAddress((void**)&pActLo, g_actLo);
    cudaGetSymbolAddress((void**)&pWbhi,  g_Wbhi);
    cudaGetSymbolAddress((void**)&pWblo,  g_Wblo);
    cudaGetSymbolAddress((void**)&pWohi,  g_Wohi);
    cudaGetSymbolAddress((void**)&pWolo,  g_Wolo);

    // pre-split inputs
    {
        long long n4 = Mm * Aa / 4;
        split_kernel<<<(unsigned)((n4 + 255) / 256), 256>>>(
            (const float4*)hptr, (ushort4*)pAhi, (ushort4*)pAlo, n4);
        n4 = (long long)Dd * Aa / 4;
        split_kernel<<<(unsigned)((n4 + 255) / 256), 256>>>(
            (const float4*)Wb, (ushort4*)pWbhi, (ushort4*)pWblo, n4);
        n4 = (long long)Vv * Dd / 4;
        split_kernel<<<(unsigned)((n4 + 255) / 256), 256>>>(
            (const float4*)Wo, (ushort4*)pWohi, (ushort4*)pWolo, n4);
    }

    const int SMEM = 3 * 61440;   // 184320 B, 3 stages
    cudaFuncSetAttribute((const void*)mma_gemm<Aa, 1>,
                         cudaFuncAttributeMaxDynamicSharedMemorySize, SMEM);
    cudaFuncSetAttribute((const void*)mma_gemm<Dd, 0>,
                         cudaFuncAttributeMaxDynamicSharedMemorySize, SMEM);

    dim3 blk(512);
    // Kernel 1: act = relu(src + tgt + hptr @ Wb^T + bb); also emits split act
    dim3 g1(Dd / 256, (unsigned)(Mm / 128));
    mma_gemm<Aa, 1><<<g1, blk, SMEM>>>(pAhi, pAlo, pWbhi, pWblo, bb, src, tgt,
                                       out_act, pActHi, pActLo, Dd);
    // Kernel 2: out = act @ Wo^T + bo
    dim3 g2(Vv / 256, (unsigned)(Mm / 128));
    mma_gemm<Dd, 0><<<g2, blk, SMEM>>>(pActHi, pActLo, pWohi, pWolo, bo,
                                       nullptr, nullptr, out_main, nullptr, nullptr, Vv);

    lengths_kernel<<<1, 32>>>(sl, tl, out + OFF_SL, out + OFF_TL);

    (void)in_sizes; (void)n_in; (void)out_size;
}